// round 2
// baseline (speedup 1.0000x reference)
#include <cuda_runtime.h>
#include <cstddef>

#define NN 16384
#define CC 10000
#define DD 128
#define LR 0.5f

// Scratch (no cudaMalloc allowed): per-class accumulators.
__device__ float g_sum[CC * DD];  // sum of preds per class
__device__ float g_cnt[CC];      // sample count per class

// ---------------------------------------------------------------------------
// Kernel 0: zero the scratch accumulators (graph replays require this every
// launch for determinism).
// ---------------------------------------------------------------------------
__global__ void cl_zero_kernel() {
    int i = blockIdx.x * blockDim.x + threadIdx.x;
    int total = CC * DD + CC;
    for (; i < total; i += gridDim.x * blockDim.x) {
        if (i < CC * DD) g_sum[i] = 0.0f;
        else             g_cnt[i - CC * DD] = 0.0f;
    }
}

// ---------------------------------------------------------------------------
// Kernel 1: one block per sample. Scan the 10000-float one-hot row with
// coalesced float4 loads to find the class index, then accumulate this
// sample's 128-dim pred vector into the class accumulator via atomicAdd.
// This kernel reads 655 MB and is the HBM-bound bulk of the runtime.
// ---------------------------------------------------------------------------
__global__ void __launch_bounds__(256) cl_scan_accum_kernel(
    const float* __restrict__ labels,   // [N, C]
    const float* __restrict__ preds)    // [N, D]
{
    __shared__ int s_cls;
    const int n = blockIdx.x;
    const int t = threadIdx.x;

    const float4* row = reinterpret_cast<const float4*>(labels + (size_t)n * CC);
    const int nvec = CC / 4;  // 2500

    int found = -1;
    #pragma unroll 4
    for (int i = t; i < nvec; i += 256) {
        float4 v = __ldg(&row[i]);
        if (v.x != 0.0f)      found = 4 * i + 0;
        else if (v.y != 0.0f) found = 4 * i + 1;
        else if (v.z != 0.0f) found = 4 * i + 2;
        else if (v.w != 0.0f) found = 4 * i + 3;
    }
    if (found >= 0) s_cls = found;  // exactly one thread finds the 1.0
    __syncthreads();

    const int c = s_cls;
    if (t < DD) {
        atomicAdd(&g_sum[(size_t)c * DD + t], __ldg(&preds[(size_t)n * DD + t]));
    }
    if (t == 0) {
        atomicAdd(&g_cnt[c], 1.0f);
    }
}

// ---------------------------------------------------------------------------
// Kernel 2: finalize.
//   grad[c] = (cnt[c]*center[c] - sum_preds[c]) / (cnt[c] + 1)
//   out[c]  = center[c] - LR * grad[c]
// Classes with no samples: cnt=0, sum=0 -> grad=0 -> out = center. Matches ref.
// ---------------------------------------------------------------------------
__global__ void __launch_bounds__(256) cl_finalize_kernel(
    const float* __restrict__ center,   // [C, D]
    float* __restrict__ out)            // [C, D]
{
    int i = blockIdx.x * blockDim.x + threadIdx.x;
    if (i >= CC * DD) return;
    int c = i / DD;
    float cnt = g_cnt[c];
    float ctr = center[i];
    float grad = (cnt * ctr - g_sum[i]) / (cnt + 1.0f);
    out[i] = ctr - LR * grad;
}

// ---------------------------------------------------------------------------
// Launch. Input order per metadata: embeded_preds [N*D], labels [N*C],
// center [C*D]. Output: updated_center [C*D] float32.
// ---------------------------------------------------------------------------
extern "C" void kernel_launch(void* const* d_in, const int* in_sizes, int n_in,
                              void* d_out, int out_size) {
    const float* preds  = (const float*)d_in[0];
    const float* labels = (const float*)d_in[1];
    const float* center = (const float*)d_in[2];
    float* out = (float*)d_out;

    (void)in_sizes; (void)n_in; (void)out_size;

    // Zero scratch: (C*D + C) elements
    {
        int total = CC * DD + CC;
        int blocks = (total + 255) / 256;
        cl_zero_kernel<<<blocks, 256>>>();
    }

    // Scan + accumulate: one block per sample
    cl_scan_accum_kernel<<<NN, 256>>>(labels, preds);

    // Finalize
    {
        int total = CC * DD;
        int blocks = (total + 255) / 256;
        cl_finalize_kernel<<<blocks, 256>>>(center, out);
    }
}

// round 5
// speedup vs baseline: 1.5937x; 1.5937x over previous
#include <cuda_runtime.h>
#include <cstddef>

#define NN 16384
#define CC 10000
#define DD 128
#define LR 0.5f

#define NVEC   (CC / 4)        // 2500 float4 per label row
#define CHUNKV 512             // float4 per chunk = 256 threads * 2 = 8KB

// Scratch (no cudaMalloc allowed). Zero-initialized at module load; the
// finalize kernel re-zeroes after each use so every graph replay starts clean.
__device__ float g_sum[CC * DD];  // per-class sum of preds
__device__ float g_cnt[CC];      // per-class sample count

// ---------------------------------------------------------------------------
// Kernel 1: one block per sample. Sequentially scan the one-hot row in 8KB
// chunks, breaking out as soon as the 1.0 is found (expected 60% of the row
// read). Then accumulate this sample's 128-dim pred vector into the class
// accumulator via red-atomics.
// ---------------------------------------------------------------------------
__global__ void __launch_bounds__(256) cl_scan_accum_kernel(
    const float* __restrict__ labels,   // [N, C]
    const float* __restrict__ preds)    // [N, D]
{
    __shared__ int s_cls;
    const int n = blockIdx.x;
    const int t = threadIdx.x;

    if (t == 0) s_cls = -1;
    __syncthreads();

    const float4* __restrict__ row =
        reinterpret_cast<const float4*>(labels + (size_t)n * CC);

    int cls = -1;
    #pragma unroll 1
    for (int base = 0; base < NVEC; base += CHUNKV) {
        const int i0 = base + t;
        const int i1 = base + t + 256;
        int found = -1;

        // Issue both loads up front (independent -> 2-deep MLP per thread).
        float4 v0, v1;
        bool p0 = (i0 < NVEC);
        bool p1 = (i1 < NVEC);
        if (p0) v0 = __ldg(&row[i0]);
        if (p1) v1 = __ldg(&row[i1]);

        if (p0) {
            if (v0.x != 0.0f)      found = 4 * i0 + 0;
            else if (v0.y != 0.0f) found = 4 * i0 + 1;
            else if (v0.z != 0.0f) found = 4 * i0 + 2;
            else if (v0.w != 0.0f) found = 4 * i0 + 3;
        }
        if (found < 0 && p1) {
            if (v1.x != 0.0f)      found = 4 * i1 + 0;
            else if (v1.y != 0.0f) found = 4 * i1 + 1;
            else if (v1.z != 0.0f) found = 4 * i1 + 2;
            else if (v1.w != 0.0f) found = 4 * i1 + 3;
        }

        if (found >= 0) s_cls = found;   // at most one thread writes, once
        __syncthreads();                 // write visible to all
        cls = s_cls;                     // uniform read
        __syncthreads();                 // reads done before any later write
        if (cls >= 0) break;             // uniform branch
    }

    const int c = cls;
    if (t < DD) {
        // Return value unused -> compiles to RED (no round trip).
        atomicAdd(&g_sum[(size_t)c * DD + t], __ldg(&preds[(size_t)n * DD + t]));
    }
    if (t == 0) {
        atomicAdd(&g_cnt[c], 1.0f);
    }
}

// ---------------------------------------------------------------------------
// Kernel 2: finalize + re-zero scratch for the next graph replay.
//   grad[c] = (cnt[c]*center[c] - sum_preds[c]) / (cnt[c] + 1)
//   out[c]  = center[c] - LR * grad[c]
// Each 256-thread block covers exactly 2 classes (D=128), so g_cnt[c] is
// read only by this block: read before the barrier, zero after it.
// ---------------------------------------------------------------------------
__global__ void __launch_bounds__(256) cl_finalize_kernel(
    const float* __restrict__ center,   // [C, D]
    float* __restrict__ out)            // [C, D]
{
    const int i = blockIdx.x * 256 + threadIdx.x;   // CC*DD divisible by 256
    const int c = i >> 7;                           // i / DD

    const float cnt = g_cnt[c];
    const float s   = g_sum[i];
    const float ctr = center[i];
    out[i] = ctr - LR * (cnt * ctr - s) / (cnt + 1.0f);

    g_sum[i] = 0.0f;                    // clean for next replay
    __syncthreads();                    // all g_cnt reads in this block done
    if ((threadIdx.x & 127) == 0) {
        g_cnt[c] = 0.0f;
    }
}

// ---------------------------------------------------------------------------
// Launch. Inputs per metadata: embeded_preds [N*D], labels [N*C],
// center [C*D]. Output: updated_center [C*D] float32.
// ---------------------------------------------------------------------------
extern "C" void kernel_launch(void* const* d_in, const int* in_sizes, int n_in,
                              void* d_out, int out_size) {
    const float* preds  = (const float*)d_in[0];
    const float* labels = (const float*)d_in[1];
    const float* center = (const float*)d_in[2];
    float* out = (float*)d_out;

    (void)in_sizes; (void)n_in; (void)out_size;

    cl_scan_accum_kernel<<<NN, 256>>>(labels, preds);
    cl_finalize_kernel<<<(CC * DD) / 256, 256>>>(center, out);
}